// round 14
// baseline (speedup 1.0000x reference)
#include <cuda_runtime.h>
#include <cuda_fp16.h>
#include <cstdint>

#define MAX_NODES 100000
#define F_DIM     16
#define K_DIM     16
#define OUT_SCALE (1.0f / 128.0f)

// Yh[k][n][16] fp16 (51.2 MB)
__device__ __half g_Yh[(size_t)K_DIM * MAX_NODES * 16];

typedef unsigned long long ull;

// ---------- packed fp32x2 helpers ----------
__device__ __forceinline__ ull pack2(float a, float b) {
    ull r;
    asm("mov.b64 %0, {%1, %2};" : "=l"(r) : "f"(a), "f"(b));
    return r;
}
__device__ __forceinline__ void fma2(ull& d, ull a, ull b) {
    asm("fma.rn.f32x2 %0, %1, %2, %3;" : "=l"(d) : "l"(a), "l"(b), "l"(d));
}
__device__ __forceinline__ ull add2(ull a, ull b) {
    ull r;
    asm("add.rn.f32x2 %0, %1, %2;" : "=l"(r) : "l"(a), "l"(b));
    return r;
}
__device__ __forceinline__ void unpack2(ull v, float& a, float& b) {
    asm("mov.b64 {%0, %1}, %2;" : "=f"(a), "=f"(b) : "l"(v));
}
__device__ __forceinline__ unsigned h2pack(float lo, float hi) {
    __half2 h = __floats2half2_rn(lo, hi);
    return *reinterpret_cast<unsigned*>(&h);
}
__device__ __forceinline__ float2 h2f(unsigned u) {
    __half2 h = *reinterpret_cast<__half2*>(&u);
    return __half22float2(h);
}

// ============================================================================
// Stage 1 (column-owner v3): thread owns (k, o-PAIR) -> W = 16 ull = 32 regs
// (half of R12/13's 64), and __launch_bounds__(256,4) forces a 64-reg budget
// -> 4 blocks/SM = 32 warps (R13: 98 regs, 2 blocks, occ 23%, issue 41% ->
// warp-starved; work needs ~17us at full issue).
// 4 FMA2 chains in flight (2 nodes x even/odd-i partials, merged with
// add.f32x2) keeps the lat-4/rt-2 FFMA2 pipe saturated.
// ============================================================================
__global__ __launch_bounds__(256, 4)
void stage1_cols(const float* __restrict__ x,
                 const float* __restrict__ W,
                 int n_nodes) {
    __shared__ ull xs2[64 * 16];    // 8 KB: xs2[node_local][i] = (x,x)

    int tid = threadIdx.x;
    int col = tid & 127;            // 0..127
    int sg  = tid >> 7;             // 0..1 (warp-uniform)
    int k   = col >> 3;             // 0..15
    int o   = (col & 7) << 1;       // 0,2,..,14
    int node_base = blockIdx.x * 64;

    // W column-pair to 16 ull registers (loaded once)
    ull w[16];
#pragma unroll
    for (int i = 0; i < 16; i++) {
        float2 wv = *reinterpret_cast<const float2*>(W + k * 256 + i * 16 + o);
        w[i] = pack2(wv.x, wv.y);
    }

    // x tile -> smem pairs
    for (int idx = tid; idx < 64 * 4; idx += 256) {
        int n = idx >> 2, q = idx & 3;
        int node = min(node_base + n, n_nodes - 1);
        float4 v = reinterpret_cast<const float4*>(x + (size_t)node * 16)[q];
        ull* dst = xs2 + n * 16 + q * 4;
        dst[0] = pack2(v.x, v.x);
        dst[1] = pack2(v.y, v.y);
        dst[2] = pack2(v.z, v.z);
        dst[3] = pack2(v.w, v.w);
    }
    __syncthreads();

    // sg covers nodes {2m+sg}; process 2 m per iter (nodes 4t+sg, 4t+2+sg)
    __half* ybase = g_Yh + ((size_t)k * n_nodes + node_base + sg) * 16 + o;

#pragma unroll 1
    for (int t = 0; t < 16; t++) {
        int nlA = t * 4 + sg;       // and nlB = nlA + 2
        const ulonglong2* xpA = reinterpret_cast<const ulonglong2*>(xs2 + nlA * 16);
        const ulonglong2* xpB = reinterpret_cast<const ulonglong2*>(xs2 + (nlA + 2) * 16);

        ull a0 = 0ull, a1 = 0ull, b0 = 0ull, b1 = 0ull;  // 4 chains
#pragma unroll
        for (int i2 = 0; i2 < 8; i2++) {
            ulonglong2 xA = xpA[i2];
            ulonglong2 xB = xpB[i2];
            fma2(a0, xA.x, w[2 * i2]);
            fma2(b0, xB.x, w[2 * i2]);
            fma2(a1, xA.y, w[2 * i2 + 1]);
            fma2(b1, xB.y, w[2 * i2 + 1]);
        }
        ull sa = add2(a0, a1);
        ull sb = add2(b0, b1);

        int nodeA = node_base + nlA;
        if (nodeA < n_nodes) {
            float p0, p1;
            unpack2(sa, p0, p1);
            *reinterpret_cast<unsigned*>(ybase + (size_t)(4 * t) * 16) =
                h2pack(p0, p1);
        }
        if (nodeA + 2 < n_nodes) {
            float p0, p1;
            unpack2(sb, p0, p1);
            *reinterpret_cast<unsigned*>(ybase + (size_t)(4 * t + 2) * 16) =
                h2pack(p0, p1);
        }
    }
}

// ============================================================================
// Stage 2 (warp-coop + reduce-scatter butterfly) — frozen at R12 (~29us)
// ============================================================================
__global__ __launch_bounds__(256)
void stage2_coop(const float2* __restrict__ edge_attr,
                 const int* __restrict__ ei,
                 const int* __restrict__ ej,
                 float* __restrict__ out,
                 int n_nodes, int n_edges) {
    const unsigned FULL = 0xFFFFFFFFu;
    int lane = threadIdx.x & 31;
    int gwarp = (blockIdx.x * 256 + threadIdx.x) >> 5;
    int g = lane >> 3;
    int r = lane & 7;
    int b = r >> 1;
    int s = r & 1;
    size_t kstride = (size_t)n_nodes * 16;

    int ebase = gwarp * 16;
    if (ebase >= n_edges) return;

    bool keep1 = (b & 1) == 0;
    bool keep2 = (b & 2) == 0;

#pragma unroll 1
    for (int it = 0; it < 4; it++) {
        int e = ebase + it * 4 + g;
        bool val = (e < n_edges);
        int eL = val ? e : 0;

        int di = ei[eL];
        int dj = ej[eL];
        float2 at = edge_attr[eL];
        val = val && (di != dj);

        float ux = fminf(fmaxf(at.x, -1.0f), 1.0f);
        float uy = fminf(fmaxf(at.y, -1.0f), 1.0f);
        float vx = (ux + 1.0f) * 1.5f;
        float vy = (uy + 1.0f) * 1.5f;
        int ca = min((int)vx, 2);
        int cb_ = min((int)vy, 2);
        float sx = vx - (float)ca;
        float ty = vy - (float)cb_;
        int k00 = ca * 4 + cb_;

        float cf = ((b & 2) ? sx : (1.0f - sx)) *
                   ((b & 1) ? ty : (1.0f - ty)) * OUT_SCALE;
        if (!val) cf = 0.0f;
        int djs = val ? dj : 0;

        int k = k00 + ((b & 2) << 1) + (b & 1);
        const uint4* p = reinterpret_cast<const uint4*>(
            g_Yh + (size_t)k * kstride + (size_t)djs * 16 + s * 8);
        uint4 Y = *p;

        float2 f0 = h2f(Y.x), f1 = h2f(Y.y), f2 = h2f(Y.z), f3 = h2f(Y.w);
        float m0 = cf * f0.x, m1 = cf * f0.y;
        float m2 = cf * f1.x, m3 = cf * f1.y;
        float m4 = cf * f2.x, m5 = cf * f2.y;
        float m6 = cf * f3.x, m7 = cf * f3.y;

        float s0_ = keep1 ? m4 : m0;
        float s1_ = keep1 ? m5 : m1;
        float s2_ = keep1 ? m6 : m2;
        float s3_ = keep1 ? m7 : m3;
        float p0 = (keep1 ? m0 : m4) + __shfl_xor_sync(FULL, s0_, 2);
        float p1 = (keep1 ? m1 : m5) + __shfl_xor_sync(FULL, s1_, 2);
        float p2 = (keep1 ? m2 : m6) + __shfl_xor_sync(FULL, s2_, 2);
        float p3 = (keep1 ? m3 : m7) + __shfl_xor_sync(FULL, s3_, 2);

        float t0 = keep2 ? p2 : p0;
        float t1 = keep2 ? p3 : p1;
        float q0 = (keep2 ? p0 : p2) + __shfl_xor_sync(FULL, t0, 4);
        float q1 = (keep2 ? p1 : p3) + __shfl_xor_sync(FULL, t1, 4);

        if (val) {
            int idx = s * 8 + (b & 1) * 4 + ((b >> 1) & 1) * 2;
            float* ob = out + (size_t)di * 16 + idx;
            asm volatile("red.global.add.v2.f32 [%0], {%1, %2};"
                         :: "l"(ob), "f"(q0), "f"(q1) : "memory");
        }
    }
}

// Aligns ncu capture (-s 5 -c 1) onto stage1 (4 launches/call)
__global__ void k_dummy() {}

extern "C" void kernel_launch(void* const* d_in, const int* in_sizes, int n_in,
                              void* d_out, int out_size) {
    const float*  x  = (const float*)d_in[0];    // [N, 16] f32
    const float2* ea = (const float2*)d_in[1];   // [E, 2]  f32
    const float*  W  = (const float*)d_in[2];    // [16,16,16] f32
    const int*    ei = (const int*)d_in[3];      // [E] int32
    const int*    ej = (const int*)d_in[4];      // [E] int32
    float* out = (float*)d_out;

    int n_nodes = in_sizes[0] / F_DIM;
    int n_edges = in_sizes[1] / 2;

    cudaMemsetAsync(d_out, 0, (size_t)out_size * sizeof(float), 0);

    stage1_cols<<<(n_nodes + 63) / 64, 256>>>(x, W, n_nodes);

    int s2_blocks = (n_edges + 127) / 128;
    stage2_coop<<<s2_blocks, 256>>>(ea, ei, ej, out, n_nodes, n_edges);
    k_dummy<<<1, 32>>>();
}

// round 15
// speedup vs baseline: 1.0579x; 1.0579x over previous
#include <cuda_runtime.h>
#include <cuda_fp16.h>
#include <cstdint>

#define MAX_NODES 100000
#define F_DIM     16
#define K_DIM     16
#define OUT_SCALE (1.0f / 128.0f)

// Yh[k][n][16] fp16 (51.2 MB)
__device__ __half g_Yh[(size_t)K_DIM * MAX_NODES * 16];

typedef unsigned long long ull;

// ---------- packed fp32x2 helpers ----------
__device__ __forceinline__ ull pack2(float a, float b) {
    ull r;
    asm("mov.b64 %0, {%1, %2};" : "=l"(r) : "f"(a), "f"(b));
    return r;
}
__device__ __forceinline__ void fma2(ull& d, ull a, ull b) {
    asm("fma.rn.f32x2 %0, %1, %2, %3;" : "=l"(d) : "l"(a), "l"(b), "l"(d));
}
__device__ __forceinline__ void unpack2(ull v, float& a, float& b) {
    asm("mov.b64 {%0, %1}, %2;" : "=f"(a), "=f"(b) : "l"(v));
}
__device__ __forceinline__ unsigned h2pack(float lo, float hi) {
    __half2 h = __floats2half2_rn(lo, hi);
    return *reinterpret_cast<unsigned*>(&h);
}
__device__ __forceinline__ float2 h2f(unsigned u) {
    __half2 h = *reinterpret_cast<__half2*>(&u);
    return __half22float2(h);
}

// ============================================================================
// Stage 1 (node-paired): acc = (y^q_o, y^{q+32}_o); FMA2 x-operand is a node
// PAIR (x_i^q, x_i^{q+32}) (LDS.64 from transposed x tile); W duplicated
// (w,w) in smem -> ZERO W registers. Warp = one k; lane = (oq, ng); 8 nodes
// per lane. Per i: 2 W-LDS.128 + 4 x-LDS.64 + 16 FMA2 (73% FMA density;
// R13 was 50% w/ 98 regs, R14 33% w/ L1@82%). Stores: 8 consecutive nodes x
// 32B contiguous = 2 wf.  regs ~56 -> 2 blocks x 512 = 8 warps/SMSP.
// ============================================================================
__global__ __launch_bounds__(512, 2)
void stage1_np(const float* __restrict__ x,
               const float* __restrict__ W,
               int n_nodes) {
    __shared__ ull   ws2[4096];      // 32 KB: [k][i][o] with (w,w) pairs
    __shared__ float xsf[16][64];    //  4 KB: [i][pos], pos 2q->node q, 2q+1->node q+32

    int tid  = threadIdx.x;
    int k    = tid >> 5;             // warp = k (0..15)
    int lane = tid & 31;
    int oq   = lane >> 3;            // 0..3 (o-quad)
    int ng   = lane & 7;             // 0..7 (node group)
    int node_base = blockIdx.x * 64;

    // Build duplicated W pairs: ws2[k*256 + i*16 + o] = (w,w)
    for (int idx = tid; idx < 2048; idx += 512) {
        float2 wv = reinterpret_cast<const float2*>(W)[idx];
        ws2[2 * idx + 0] = pack2(wv.x, wv.x);
        ws2[2 * idx + 1] = pack2(wv.y, wv.y);
    }
    // Build transposed x tile (node pairing (q, q+32))
    for (int idx = tid; idx < 256; idx += 512) {
        int n = idx >> 2, qq = idx & 3;
        int node = min(node_base + n, n_nodes - 1);
        float4 v = reinterpret_cast<const float4*>(x + (size_t)node * 16)[qq];
        int pos = (n < 32) ? (2 * n) : (2 * (n - 32) + 1);
        xsf[qq * 4 + 0][pos] = v.x;
        xsf[qq * 4 + 1][pos] = v.y;
        xsf[qq * 4 + 2][pos] = v.z;
        xsf[qq * 4 + 3][pos] = v.w;
    }
    __syncthreads();

    ull acc[4][4];   // [m][o] ; pair m = nodes (ng+8m, ng+8m+32)
#pragma unroll
    for (int m = 0; m < 4; m++)
#pragma unroll
        for (int o = 0; o < 4; o++) acc[m][o] = 0ull;

    const ull* wrow = ws2 + k * 256 + oq * 4;

#pragma unroll
    for (int i = 0; i < 16; i++) {
        ulonglong2 wA = *reinterpret_cast<const ulonglong2*>(wrow + i * 16);
        ulonglong2 wB = *reinterpret_cast<const ulonglong2*>(wrow + i * 16 + 2);
        ull x0 = *reinterpret_cast<const ull*>(&xsf[i][2 * (ng + 0)]);
        ull x1 = *reinterpret_cast<const ull*>(&xsf[i][2 * (ng + 8)]);
        ull x2 = *reinterpret_cast<const ull*>(&xsf[i][2 * (ng + 16)]);
        ull x3 = *reinterpret_cast<const ull*>(&xsf[i][2 * (ng + 24)]);

        fma2(acc[0][0], x0, wA.x);
        fma2(acc[1][0], x1, wA.x);
        fma2(acc[2][0], x2, wA.x);
        fma2(acc[3][0], x3, wA.x);
        fma2(acc[0][1], x0, wA.y);
        fma2(acc[1][1], x1, wA.y);
        fma2(acc[2][1], x2, wA.y);
        fma2(acc[3][1], x3, wA.y);
        fma2(acc[0][2], x0, wB.x);
        fma2(acc[1][2], x1, wB.x);
        fma2(acc[2][2], x2, wB.x);
        fma2(acc[3][2], x3, wB.x);
        fma2(acc[0][3], x0, wB.y);
        fma2(acc[1][3], x1, wB.y);
        fma2(acc[2][3], x2, wB.y);
        fma2(acc[3][3], x3, wB.y);
    }

    // Stores: lo half -> node ng+8m, hi half -> node ng+8m+32
#pragma unroll
    for (int m = 0; m < 4; m++) {
        float lo0, hi0, lo1, hi1, lo2, hi2, lo3, hi3;
        unpack2(acc[m][0], lo0, hi0);
        unpack2(acc[m][1], lo1, hi1);
        unpack2(acc[m][2], lo2, hi2);
        unpack2(acc[m][3], lo3, hi3);

        int nodeL = node_base + ng + 8 * m;
        if (nodeL < n_nodes) {
            unsigned a = h2pack(lo0, lo1), b = h2pack(lo2, lo3);
            ull payload;
            asm("mov.b64 %0, {%1, %2};" : "=l"(payload) : "r"(a), "r"(b));
            *reinterpret_cast<ull*>(
                g_Yh + ((size_t)k * n_nodes + nodeL) * 16 + oq * 4) = payload;
        }
        int nodeH = nodeL + 32;
        if (nodeH < n_nodes) {
            unsigned a = h2pack(hi0, hi1), b = h2pack(hi2, hi3);
            ull payload;
            asm("mov.b64 %0, {%1, %2};" : "=l"(payload) : "r"(a), "r"(b));
            *reinterpret_cast<ull*>(
                g_Yh + ((size_t)k * n_nodes + nodeH) * 16 + oq * 4) = payload;
        }
    }
}

// ============================================================================
// Stage 2 (warp-coop + reduce-scatter butterfly) — frozen at R12 (~28us)
// ============================================================================
__global__ __launch_bounds__(256)
void stage2_coop(const float2* __restrict__ edge_attr,
                 const int* __restrict__ ei,
                 const int* __restrict__ ej,
                 float* __restrict__ out,
                 int n_nodes, int n_edges) {
    const unsigned FULL = 0xFFFFFFFFu;
    int lane = threadIdx.x & 31;
    int gwarp = (blockIdx.x * 256 + threadIdx.x) >> 5;
    int g = lane >> 3;
    int r = lane & 7;
    int b = r >> 1;
    int s = r & 1;
    size_t kstride = (size_t)n_nodes * 16;

    int ebase = gwarp * 16;
    if (ebase >= n_edges) return;

    bool keep1 = (b & 1) == 0;
    bool keep2 = (b & 2) == 0;

#pragma unroll 1
    for (int it = 0; it < 4; it++) {
        int e = ebase + it * 4 + g;
        bool val = (e < n_edges);
        int eL = val ? e : 0;

        int di = ei[eL];
        int dj = ej[eL];
        float2 at = edge_attr[eL];
        val = val && (di != dj);

        float ux = fminf(fmaxf(at.x, -1.0f), 1.0f);
        float uy = fminf(fmaxf(at.y, -1.0f), 1.0f);
        float vx = (ux + 1.0f) * 1.5f;
        float vy = (uy + 1.0f) * 1.5f;
        int ca = min((int)vx, 2);
        int cb_ = min((int)vy, 2);
        float sx = vx - (float)ca;
        float ty = vy - (float)cb_;
        int k00 = ca * 4 + cb_;

        float cf = ((b & 2) ? sx : (1.0f - sx)) *
                   ((b & 1) ? ty : (1.0f - ty)) * OUT_SCALE;
        if (!val) cf = 0.0f;
        int djs = val ? dj : 0;

        int k = k00 + ((b & 2) << 1) + (b & 1);
        const uint4* p = reinterpret_cast<const uint4*>(
            g_Yh + (size_t)k * kstride + (size_t)djs * 16 + s * 8);
        uint4 Y = *p;

        float2 f0 = h2f(Y.x), f1 = h2f(Y.y), f2 = h2f(Y.z), f3 = h2f(Y.w);
        float m0 = cf * f0.x, m1 = cf * f0.y;
        float m2 = cf * f1.x, m3 = cf * f1.y;
        float m4 = cf * f2.x, m5 = cf * f2.y;
        float m6 = cf * f3.x, m7 = cf * f3.y;

        float s0_ = keep1 ? m4 : m0;
        float s1_ = keep1 ? m5 : m1;
        float s2_ = keep1 ? m6 : m2;
        float s3_ = keep1 ? m7 : m3;
        float p0 = (keep1 ? m0 : m4) + __shfl_xor_sync(FULL, s0_, 2);
        float p1 = (keep1 ? m1 : m5) + __shfl_xor_sync(FULL, s1_, 2);
        float p2 = (keep1 ? m2 : m6) + __shfl_xor_sync(FULL, s2_, 2);
        float p3 = (keep1 ? m3 : m7) + __shfl_xor_sync(FULL, s3_, 2);

        float t0 = keep2 ? p2 : p0;
        float t1 = keep2 ? p3 : p1;
        float q0 = (keep2 ? p0 : p2) + __shfl_xor_sync(FULL, t0, 4);
        float q1 = (keep2 ? p1 : p3) + __shfl_xor_sync(FULL, t1, 4);

        if (val) {
            int idx = s * 8 + (b & 1) * 4 + ((b >> 1) & 1) * 2;
            float* ob = out + (size_t)di * 16 + idx;
            asm volatile("red.global.add.v2.f32 [%0], {%1, %2};"
                         :: "l"(ob), "f"(q0), "f"(q1) : "memory");
        }
    }
}

// Aligns ncu capture (-s 5 -c 1) onto stage1 (4 launches/call)
__global__ void k_dummy() {}

extern "C" void kernel_launch(void* const* d_in, const int* in_sizes, int n_in,
                              void* d_out, int out_size) {
    const float*  x  = (const float*)d_in[0];    // [N, 16] f32
    const float2* ea = (const float2*)d_in[1];   // [E, 2]  f32
    const float*  W  = (const float*)d_in[2];    // [16,16,16] f32
    const int*    ei = (const int*)d_in[3];      // [E] int32
    const int*    ej = (const int*)d_in[4];      // [E] int32
    float* out = (float*)d_out;

    int n_nodes = in_sizes[0] / F_DIM;
    int n_edges = in_sizes[1] / 2;

    cudaMemsetAsync(d_out, 0, (size_t)out_size * sizeof(float), 0);

    stage1_np<<<(n_nodes + 63) / 64, 512>>>(x, W, n_nodes);

    int s2_blocks = (n_edges + 127) / 128;
    stage2_coop<<<s2_blocks, 256>>>(ea, ei, ej, out, n_nodes, n_edges);
    k_dummy<<<1, 32>>>();
}

// round 16
// speedup vs baseline: 1.2772x; 1.2073x over previous
#include <cuda_runtime.h>
#include <cuda_fp16.h>
#include <cstdint>

#define MAX_NODES 100000
#define F_DIM     16
#define K_DIM     16
#define OUT_SCALE (1.0f / 128.0f)

// Yh[k][n][16] fp16 (51.2 MB)
__device__ __half g_Yh[(size_t)K_DIM * MAX_NODES * 16];

typedef unsigned long long ull;

__device__ __forceinline__ float2 h2f(unsigned u) {
    __half2 h = *reinterpret_cast<__half2*>(&u);
    return __half22float2(h);
}
__device__ __forceinline__ unsigned hp2(float a, float b) {
    __half2 h = __floats2half2_rn(a, b);
    return *reinterpret_cast<unsigned*>(&h);
}
__device__ __forceinline__ unsigned hfma2u(unsigned a, unsigned b, unsigned c) {
    __half2 r = __hfma2(*reinterpret_cast<__half2*>(&a),
                        *reinterpret_cast<__half2*>(&b),
                        *reinterpret_cast<__half2*>(&c));
    return *reinterpret_cast<unsigned*>(&r);
}

// ============================================================================
// Stage 1 (HFMA2): Yh[k][n][:] = fp16( x_h[n] @ W_h[k] ).
// Rationale: FFMA2 (64-bit operands) hits the RF-banking rt=3 wall (3 even +
// 3 odd distinct regs) -> ~18.5us pipe floor; measured 32.5us across 4
// variants with issue pinned ~41%. HFMA2 operands are single 32-bit regs ->
// rt=2 -> 12.3us floor, and acc is fp16x2 (8 regs) so the epilogue is plain
// coalesced STG.128 with no packing.
// Block 512 = 16 warps; warp = k; lane = node; 64-node tile (2 per lane).
// smem: W as half2 output-pairs (8KB, broadcast reads), x as (h,h) half2
// (4KB, conflict-free per-lane reads).
// ============================================================================
__global__ __launch_bounds__(512)
void stage1_h(const float* __restrict__ x,
              const float* __restrict__ W,
              int n_nodes) {
    __shared__ unsigned wsh[2048];      // 8 KB: [k][i][op] = (W[k][i][2op], W[k][i][2op+1])
    __shared__ unsigned xsh[16][64];    // 4 KB: [i][nl] = (x_h, x_h)

    int tid  = threadIdx.x;
    int k    = tid >> 5;                // warp = k
    int lane = tid & 31;
    int node_base = blockIdx.x * 64;

    // W -> half2 pairs
#pragma unroll
    for (int e = tid; e < 2048; e += 512) {
        int kk = e >> 7;
        int rem = e & 127;
        int i = rem >> 3;
        int op = rem & 7;
        float2 wv = *reinterpret_cast<const float2*>(W + kk * 256 + i * 16 + 2 * op);
        wsh[e] = hp2(wv.x, wv.y);
    }
    // x -> duplicated half2
#pragma unroll
    for (int idx = tid; idx < 256; idx += 512) {
        int n = idx >> 2, q = idx & 3;
        int node = min(node_base + n, n_nodes - 1);
        float4 v = reinterpret_cast<const float4*>(x + (size_t)node * 16)[q];
        xsh[4 * q + 0][n] = hp2(v.x, v.x);
        xsh[4 * q + 1][n] = hp2(v.y, v.y);
        xsh[4 * q + 2][n] = hp2(v.z, v.z);
        xsh[4 * q + 3][n] = hp2(v.w, v.w);
    }
    __syncthreads();

    unsigned accA[8], accB[8];          // nodes (lane) and (lane+32)
#pragma unroll
    for (int j = 0; j < 8; j++) { accA[j] = 0u; accB[j] = 0u; }

    const uint4* wrow = reinterpret_cast<const uint4*>(wsh + k * 128);

#pragma unroll
    for (int i = 0; i < 16; i++) {
        uint4 w0 = wrow[i * 2 + 0];     // ops 0..3  (broadcast)
        uint4 w1 = wrow[i * 2 + 1];     // ops 4..7
        unsigned xa = xsh[i][lane];
        unsigned xb = xsh[i][lane + 32];
        accA[0] = hfma2u(xa, w0.x, accA[0]);
        accB[0] = hfma2u(xb, w0.x, accB[0]);
        accA[1] = hfma2u(xa, w0.y, accA[1]);
        accB[1] = hfma2u(xb, w0.y, accB[1]);
        accA[2] = hfma2u(xa, w0.z, accA[2]);
        accB[2] = hfma2u(xb, w0.z, accB[2]);
        accA[3] = hfma2u(xa, w0.w, accA[3]);
        accB[3] = hfma2u(xb, w0.w, accB[3]);
        accA[4] = hfma2u(xa, w1.x, accA[4]);
        accB[4] = hfma2u(xb, w1.x, accB[4]);
        accA[5] = hfma2u(xa, w1.y, accA[5]);
        accB[5] = hfma2u(xb, w1.y, accB[5]);
        accA[6] = hfma2u(xa, w1.z, accA[6]);
        accB[6] = hfma2u(xb, w1.z, accB[6]);
        accA[7] = hfma2u(xa, w1.w, accA[7]);
        accB[7] = hfma2u(xb, w1.w, accB[7]);
    }

    // stores: acc IS the fp16 payload; warp writes 32 consecutive 32B rows
    int nodeA = node_base + lane;
    if (nodeA < n_nodes) {
        uint4* yo = reinterpret_cast<uint4*>(
            g_Yh + ((size_t)k * n_nodes + nodeA) * 16);
        yo[0] = make_uint4(accA[0], accA[1], accA[2], accA[3]);
        yo[1] = make_uint4(accA[4], accA[5], accA[6], accA[7]);
    }
    int nodeB = nodeA + 32;
    if (nodeB < n_nodes) {
        uint4* yo = reinterpret_cast<uint4*>(
            g_Yh + ((size_t)k * n_nodes + nodeB) * 16);
        yo[0] = make_uint4(accB[0], accB[1], accB[2], accB[3]);
        yo[1] = make_uint4(accB[4], accB[5], accB[6], accB[7]);
    }
}

// ============================================================================
// Stage 2 (warp-coop + reduce-scatter butterfly) — frozen (~28us)
// ============================================================================
__global__ __launch_bounds__(256)
void stage2_coop(const float2* __restrict__ edge_attr,
                 const int* __restrict__ ei,
                 const int* __restrict__ ej,
                 float* __restrict__ out,
                 int n_nodes, int n_edges) {
    const unsigned FULL = 0xFFFFFFFFu;
    int lane = threadIdx.x & 31;
    int gwarp = (blockIdx.x * 256 + threadIdx.x) >> 5;
    int g = lane >> 3;
    int r = lane & 7;
    int b = r >> 1;
    int s = r & 1;
    size_t kstride = (size_t)n_nodes * 16;

    int ebase = gwarp * 16;
    if (ebase >= n_edges) return;

    bool keep1 = (b & 1) == 0;
    bool keep2 = (b & 2) == 0;

#pragma unroll 1
    for (int it = 0; it < 4; it++) {
        int e = ebase + it * 4 + g;
        bool val = (e < n_edges);
        int eL = val ? e : 0;

        int di = ei[eL];
        int dj = ej[eL];
        float2 at = edge_attr[eL];
        val = val && (di != dj);

        float ux = fminf(fmaxf(at.x, -1.0f), 1.0f);
        float uy = fminf(fmaxf(at.y, -1.0f), 1.0f);
        float vx = (ux + 1.0f) * 1.5f;
        float vy = (uy + 1.0f) * 1.5f;
        int ca = min((int)vx, 2);
        int cb_ = min((int)vy, 2);
        float sx = vx - (float)ca;
        float ty = vy - (float)cb_;
        int k00 = ca * 4 + cb_;

        float cf = ((b & 2) ? sx : (1.0f - sx)) *
                   ((b & 1) ? ty : (1.0f - ty)) * OUT_SCALE;
        if (!val) cf = 0.0f;
        int djs = val ? dj : 0;

        int k = k00 + ((b & 2) << 1) + (b & 1);
        const uint4* p = reinterpret_cast<const uint4*>(
            g_Yh + (size_t)k * kstride + (size_t)djs * 16 + s * 8);
        uint4 Y = *p;

        float2 f0 = h2f(Y.x), f1 = h2f(Y.y), f2 = h2f(Y.z), f3 = h2f(Y.w);
        float m0 = cf * f0.x, m1 = cf * f0.y;
        float m2 = cf * f1.x, m3 = cf * f1.y;
        float m4 = cf * f2.x, m5 = cf * f2.y;
        float m6 = cf * f3.x, m7 = cf * f3.y;

        float s0_ = keep1 ? m4 : m0;
        float s1_ = keep1 ? m5 : m1;
        float s2_ = keep1 ? m6 : m2;
        float s3_ = keep1 ? m7 : m3;
        float p0 = (keep1 ? m0 : m4) + __shfl_xor_sync(FULL, s0_, 2);
        float p1 = (keep1 ? m1 : m5) + __shfl_xor_sync(FULL, s1_, 2);
        float p2 = (keep1 ? m2 : m6) + __shfl_xor_sync(FULL, s2_, 2);
        float p3 = (keep1 ? m3 : m7) + __shfl_xor_sync(FULL, s3_, 2);

        float t0 = keep2 ? p2 : p0;
        float t1 = keep2 ? p3 : p1;
        float q0 = (keep2 ? p0 : p2) + __shfl_xor_sync(FULL, t0, 4);
        float q1 = (keep2 ? p1 : p3) + __shfl_xor_sync(FULL, t1, 4);

        if (val) {
            int idx = s * 8 + (b & 1) * 4 + ((b >> 1) & 1) * 2;
            float* ob = out + (size_t)di * 16 + idx;
            asm volatile("red.global.add.v2.f32 [%0], {%1, %2};"
                         :: "l"(ob), "f"(q0), "f"(q1) : "memory");
        }
    }
}

// Aligns ncu capture (-s 5 -c 1) onto stage1 (4 launches/call)
__global__ void k_dummy() {}

extern "C" void kernel_launch(void* const* d_in, const int* in_sizes, int n_in,
                              void* d_out, int out_size) {
    const float*  x  = (const float*)d_in[0];    // [N, 16] f32
    const float2* ea = (const float2*)d_in[1];   // [E, 2]  f32
    const float*  W  = (const float*)d_in[2];    // [16,16,16] f32
    const int*    ei = (const int*)d_in[3];      // [E] int32
    const int*    ej = (const int*)d_in[4];      // [E] int32
    float* out = (float*)d_out;

    int n_nodes = in_sizes[0] / F_DIM;
    int n_edges = in_sizes[1] / 2;

    cudaMemsetAsync(d_out, 0, (size_t)out_size * sizeof(float), 0);

    stage1_h<<<(n_nodes + 63) / 64, 512>>>(x, W, n_nodes);

    int s2_blocks = (n_edges + 127) / 128;
    stage2_coop<<<s2_blocks, 256>>>(ea, ei, ej, out, n_nodes, n_edges);
    k_dummy<<<1, 32>>>();
}